// round 6
// baseline (speedup 1.0000x reference)
#include <cuda_runtime.h>
#include <math.h>
#include <stdint.h>

#define Bsz 2
#define Tt  2048
#define Cc  1024
#define Hh  16
#define KVh 4
#define HDim 64
#define QKVN 1536   // 1024 Q + 256 K + 256 V

// -------- scratch (static device globals; no allocation) --------
__device__ float g_Xtf[Bsz * Tt * Cc];         // x pre-converted to tf32 bits
__device__ float g_QKV[Bsz * Tt * QKVN];       // fused Q|K|V rows (fp32)
__device__ float g_Y[Bsz * Tt * Hh * HDim];    // attention out (tf32 bits)
__device__ float g_WqkvT[QKVN * Cc];           // transposed + tf32 bits
__device__ float g_WoT[Cc * Cc];               // transposed + tf32 bits

__device__ __forceinline__ uint32_t f2tf32(float f) {
    uint32_t r;
    asm("cvt.rna.tf32.f32 %0, %1;" : "=r"(r) : "f"(f));
    return r;
}
__device__ __forceinline__ float tf(float f) { return __uint_as_float(f2tf32(f)); }

__device__ __forceinline__ void mma_tf32(float* c, const uint32_t* a, const uint32_t* b) {
    asm volatile(
        "mma.sync.aligned.m16n8k8.row.col.f32.tf32.tf32.f32 "
        "{%0,%1,%2,%3}, {%4,%5,%6,%7}, {%8,%9}, {%0,%1,%2,%3};"
        : "+f"(c[0]), "+f"(c[1]), "+f"(c[2]), "+f"(c[3])
        : "r"(a[0]), "r"(a[1]), "r"(a[2]), "r"(a[3]), "r"(b[0]), "r"(b[1]));
}

__device__ __forceinline__ void cpa16(float* s, const float* g) {
    uint32_t sa = (uint32_t)__cvta_generic_to_shared(s);
    asm volatile("cp.async.ca.shared.global [%0], [%1], 16;" :: "r"(sa), "l"(g));
}
#define CP_COMMIT() asm volatile("cp.async.commit_group;" ::: "memory")
#define CP_WAIT(n)  asm volatile("cp.async.wait_group %0;" :: "n"(n) : "memory")

// ============================================================
// x -> tf32 bits (vectorized)
// ============================================================
__global__ __launch_bounds__(256) void cvt_x(
    const float* __restrict__ in, float* __restrict__ out)
{
    int i = blockIdx.x * blockDim.x + threadIdx.x;
    float4 v = *(const float4*)(in + (size_t)i * 4);
    float4 o = { tf(v.x), tf(v.y), tf(v.z), tf(v.w) };
    *(float4*)(out + (size_t)i * 4) = o;
}

// ============================================================
// Fused QKV weight transpose + tf32 cvt:
// Wq[1024,1024], Wk[1024,256], Wv[1024,256] -> WqkvT[1536,1024]
// ============================================================
__global__ __launch_bounds__(256) void transpose_qkv(
    const float* __restrict__ Wq, const float* __restrict__ Wk,
    const float* __restrict__ Wv, float* __restrict__ out)
{
    __shared__ float tile[32][33];
    int nblk = blockIdx.x;       // 0..47
    int k0 = blockIdx.y * 32;
    int tx = threadIdx.x, ty = threadIdx.y;

    const float* src;
    int N, nloc;
    if (nblk < 32)      { src = Wq; N = 1024; nloc = nblk * 32; }
    else if (nblk < 40) { src = Wk; N = 256;  nloc = (nblk - 32) * 32; }
    else                { src = Wv; N = 256;  nloc = (nblk - 40) * 32; }

#pragma unroll
    for (int i = 0; i < 32; i += 8)
        tile[ty + i][tx] = src[(size_t)(k0 + ty + i) * N + nloc + tx];
    __syncthreads();
#pragma unroll
    for (int i = 0; i < 32; i += 8)
        out[(size_t)(nblk * 32 + ty + i) * Cc + k0 + tx] = tf(tile[tx][ty + i]);
}

// ============================================================
// Single weight transpose + tf32 cvt: in[K,N] -> out[N,K]
// ============================================================
__global__ __launch_bounds__(256) void transpose_k(
    const float* __restrict__ in, float* __restrict__ out, int K, int N)
{
    __shared__ float tile[32][33];
    int k0 = blockIdx.y * 32, n0 = blockIdx.x * 32;
    int tx = threadIdx.x, ty = threadIdx.y;
#pragma unroll
    for (int i = 0; i < 32; i += 8)
        tile[ty + i][tx] = in[(size_t)(k0 + ty + i) * N + n0 + tx];
    __syncthreads();
#pragma unroll
    for (int i = 0; i < 32; i += 8)
        out[(size_t)(n0 + ty + i) * K + k0 + tx] = tf(tile[tx][ty + i]);
}

// ============================================================
// Pipelined tf32 mma.sync GEMM: C[M,N] = A[M,K] @ BT[N,K]^T
// A/BT hold tf32-rounded bits. 128x128 tile, 256 thr,
// K-chunk 32, 3-stage cp.async, ONE barrier per chunk.
// ============================================================
#define SMS 36
#define STAGE_F (2 * 128 * SMS)
#define GEMM_SMEM (3 * STAGE_F * 4)      // 110592 bytes

__global__ __launch_bounds__(256, 2) void gemm_mma(
    const float* __restrict__ A, const float* __restrict__ BT,
    float* __restrict__ C, int M, int N, int K)
{
    extern __shared__ float sh[];

    int tid = threadIdx.x;
    int wid = tid >> 5;
    int lane = tid & 31;
    int gr = lane >> 2;
    int gc = lane & 3;
    int bm = blockIdx.y * 128, bn = blockIdx.x * 128;
    int m0 = (wid & 1) * 64;
    int n0 = (wid >> 1) * 32;

    const int crow = tid >> 3;
    const int ccol = (tid & 7) * 4;

    float acc[4][4][4];
#pragma unroll
    for (int mt = 0; mt < 4; mt++)
#pragma unroll
        for (int nt = 0; nt < 4; nt++)
#pragma unroll
            for (int i = 0; i < 4; i++) acc[mt][nt][i] = 0.f;

    auto issue = [&](int s, int kc) {
        float* As = sh + s * STAGE_F;
        float* Bs = As + 128 * SMS;
#pragma unroll
        for (int i = 0; i < 4; i++) {
            int row = i * 32 + crow;
            cpa16(&As[row * SMS + ccol], A  + (size_t)(bm + row) * K + kc + ccol);
            cpa16(&Bs[row * SMS + ccol], BT + (size_t)(bn + row) * K + kc + ccol);
        }
        CP_COMMIT();
    };

    const int NCH = K / 32;
    issue(0, 0);
    issue(1, 32);

    int s = 0;
    for (int c = 0; c < NCH; c++) {
        if (c == NCH - 1) { CP_WAIT(0); } else { CP_WAIT(1); }
        __syncthreads();
        if (c + 2 < NCH) {
            int s2 = s + 2; if (s2 >= 3) s2 -= 3;
            issue(s2, (c + 2) * 32);
        }

        const float* As = sh + s * STAGE_F;
        const float* Bs = As + 128 * SMS;
#pragma unroll
        for (int ks = 0; ks < 4; ks++) {
            int k0 = ks * 8;
            uint32_t af[4][4], bf[4][2];
#pragma unroll
            for (int mt = 0; mt < 4; mt++) {
                const float* base = &As[(m0 + mt * 16 + gr) * SMS + k0 + gc];
                af[mt][0] = __float_as_uint(base[0]);
                af[mt][1] = __float_as_uint(base[8 * SMS]);
                af[mt][2] = __float_as_uint(base[4]);
                af[mt][3] = __float_as_uint(base[8 * SMS + 4]);
            }
#pragma unroll
            for (int nt = 0; nt < 4; nt++) {
                const float* base = &Bs[(n0 + nt * 8 + gr) * SMS + k0 + gc];
                bf[nt][0] = __float_as_uint(base[0]);
                bf[nt][1] = __float_as_uint(base[4]);
            }
#pragma unroll
            for (int mt = 0; mt < 4; mt++)
#pragma unroll
                for (int nt = 0; nt < 4; nt++)
                    mma_tf32(acc[mt][nt], af[mt], bf[nt]);
        }
        if (++s >= 3) s -= 3;
    }

#pragma unroll
    for (int mt = 0; mt < 4; mt++) {
#pragma unroll
        for (int nt = 0; nt < 4; nt++) {
            int row = bm + m0 + mt * 16 + gr;
            int col = bn + n0 + nt * 8 + 2 * gc;
            *(float2*)&C[(size_t)row * N + col] =
                make_float2(acc[mt][nt][0], acc[mt][nt][1]);
            *(float2*)&C[(size_t)(row + 8) * N + col] =
                make_float2(acc[mt][nt][2], acc[mt][nt][3]);
        }
    }
}

// ============================================================
// RoPE + RMSNorm over fused QKV buffer (stride QKVN).
// ============================================================
__global__ __launch_bounds__(256) void rope_rms(
    float* __restrict__ QKV,
    const float* __restrict__ cosp, const float* __restrict__ sinp)
{
    int gw = (blockIdx.x * blockDim.x + threadIdx.x) >> 5;
    int lane = threadIdx.x & 31;
    const int total_q = Bsz * Tt * Hh;

    float* p;
    int t;
    if (gw < total_q) {
        int bt = gw / Hh, h = gw % Hh;
        t = bt % Tt;
        p = QKV + (size_t)bt * QKVN + h * HDim;
    } else {
        int g = gw - total_q;
        int bt = g / KVh, kv = g % KVh;
        t = bt % Tt;
        p = QKV + (size_t)bt * QKVN + 1024 + kv * HDim;
    }

    float c = cosp[t * (HDim / 2) + lane];
    float s = sinp[t * (HDim / 2) + lane];
    float x1 = p[lane];
    float x2 = p[lane + 32];
    float o1 = x1 * c + x2 * s;
    float o2 = -x1 * s + x2 * c;

    float ss = o1 * o1 + o2 * o2;
#pragma unroll
    for (int off = 16; off > 0; off >>= 1)
        ss += __shfl_xor_sync(0xffffffffu, ss, off);

    float inv = rsqrtf(ss * (1.0f / HDim) + 1e-6f);
    p[lane]      = o1 * inv;
    p[lane + 32] = o2 * inv;
}

// ============================================================
// tf32 mma.sync causal GQA flash attention (reads fused QKV).
// Output written tf32-rounded (feeds Wo GEMM directly).
// ============================================================
#define AST 68

__global__ __launch_bounds__(256) void flash_attn_mma(
    const float* __restrict__ QKV, float* __restrict__ Og)
{
    extern __shared__ float sm[];
    float* Qs = sm;
    float* Ks = sm + 128 * AST;
    float* Vs = Ks + 64 * AST;

    int qb = blockIdx.x, h = blockIdx.y, b = blockIdx.z;
    int q0 = qb * 128;
    int kvh = h >> 2;
    int tid = threadIdx.x, wid = tid >> 5, lane = tid & 31;
    int gr = lane >> 2, gc = lane & 3;
    int m0 = wid * 16;

    const float* Qbase = QKV + (size_t)(b * Tt + q0) * QKVN + h * HDim;
#pragma unroll
    for (int i = 0; i < 8; i++) {
        int fi = i * 256 + tid;
        int row = fi >> 4, c4 = (fi & 15) * 4;
        float4 v = *(const float4*)(Qbase + (size_t)row * QKVN + c4);
        float* d = &Qs[row * AST + c4];
        d[0] = tf(v.x * 0.125f); d[1] = tf(v.y * 0.125f);
        d[2] = tf(v.z * 0.125f); d[3] = tf(v.w * 0.125f);
    }
    __syncthreads();

    uint32_t qf[8][4];
#pragma unroll
    for (int ks = 0; ks < 8; ks++) {
        const float* p0 = &Qs[(m0 + gr) * AST + ks * 8 + gc];
        qf[ks][0] = __float_as_uint(p0[0]);
        qf[ks][1] = __float_as_uint(p0[8 * AST]);
        qf[ks][2] = __float_as_uint(p0[4]);
        qf[ks][3] = __float_as_uint(p0[8 * AST + 4]);
    }

    float o[8][4];
#pragma unroll
    for (int nt = 0; nt < 8; nt++)
#pragma unroll
        for (int i = 0; i < 4; i++) o[nt][i] = 0.f;
    float m_lo = -1e30f, m_hi = -1e30f, l_lo = 0.f, l_hi = 0.f;

    const int row_lo = q0 + m0 + gr;
    const int row_hi = row_lo + 8;
    const int nkt = 2 * qb + 2;

    for (int kt = 0; kt < nkt; kt++) {
        int kv0 = kt * 64;
        __syncthreads();

        const float* Kbase = QKV + (size_t)(b * Tt + kv0) * QKVN + 1024 + kvh * HDim;
        const float* Vbase = Kbase + 256;
#pragma unroll
        for (int i = 0; i < 4; i++) {
            int fi = i * 256 + tid;
            int row = fi >> 4, c4 = (fi & 15) * 4;
            size_t g = (size_t)row * QKVN + c4;
            float4 kv = *(const float4*)(Kbase + g);
            float4 vv = *(const float4*)(Vbase + g);
            float* dk = &Ks[row * AST + c4];
            float* dv = &Vs[row * AST + c4];
            dk[0] = tf(kv.x); dk[1] = tf(kv.y); dk[2] = tf(kv.z); dk[3] = tf(kv.w);
            dv[0] = tf(vv.x); dv[1] = tf(vv.y); dv[2] = tf(vv.z); dv[3] = tf(vv.w);
        }
        __syncthreads();

        float s[8][4];
#pragma unroll
        for (int nt = 0; nt < 8; nt++)
#pragma unroll
            for (int i = 0; i < 4; i++) s[nt][i] = 0.f;

#pragma unroll
        for (int ks = 0; ks < 8; ks++) {
#pragma unroll
            for (int nt = 0; nt < 8; nt++) {
                uint32_t bf[2];
                const float* bp = &Ks[(nt * 8 + gr) * AST + ks * 8 + gc];
                bf[0] = __float_as_uint(bp[0]);
                bf[1] = __float_as_uint(bp[4]);
                mma_tf32(s[nt], qf[ks], bf);
            }
        }

        if (kv0 + 63 > q0) {
#pragma unroll
            for (int nt = 0; nt < 8; nt++) {
                int c0 = kv0 + nt * 8 + 2 * gc;
                if (c0 > row_lo)     s[nt][0] = -1e30f;
                if (c0 + 1 > row_lo) s[nt][1] = -1e30f;
                if (c0 > row_hi)     s[nt][2] = -1e30f;
                if (c0 + 1 > row_hi) s[nt][3] = -1e30f;
            }
        }

        float tlo = -1e30f, thi = -1e30f;
#pragma unroll
        for (int nt = 0; nt < 8; nt++) {
            tlo = fmaxf(tlo, fmaxf(s[nt][0], s[nt][1]));
            thi = fmaxf(thi, fmaxf(s[nt][2], s[nt][3]));
        }
        tlo = fmaxf(tlo, __shfl_xor_sync(0xffffffffu, tlo, 1));
        tlo = fmaxf(tlo, __shfl_xor_sync(0xffffffffu, tlo, 2));
        thi = fmaxf(thi, __shfl_xor_sync(0xffffffffu, thi, 1));
        thi = fmaxf(thi, __shfl_xor_sync(0xffffffffu, thi, 2));

        float mn_lo = fmaxf(m_lo, tlo);
        float mn_hi = fmaxf(m_hi, thi);
        float cor_lo = __expf(m_lo - mn_lo);
        float cor_hi = __expf(m_hi - mn_hi);
        m_lo = mn_lo; m_hi = mn_hi;
        l_lo *= cor_lo; l_hi *= cor_hi;
#pragma unroll
        for (int nt = 0; nt < 8; nt++) {
            o[nt][0] *= cor_lo; o[nt][1] *= cor_lo;
            o[nt][2] *= cor_hi; o[nt][3] *= cor_hi;
        }

        float* Ps = Qs;
#pragma unroll
        for (int nt = 0; nt < 8; nt++) {
            float p0 = __expf(s[nt][0] - m_lo);
            float p1 = __expf(s[nt][1] - m_lo);
            float p2 = __expf(s[nt][2] - m_hi);
            float p3 = __expf(s[nt][3] - m_hi);
            l_lo += p0 + p1;
            l_hi += p2 + p3;
            *(float2*)&Ps[(m0 + gr) * AST + nt * 8 + 2 * gc] =
                make_float2(tf(p0), tf(p1));
            *(float2*)&Ps[(m0 + 8 + gr) * AST + nt * 8 + 2 * gc] =
                make_float2(tf(p2), tf(p3));
        }
        __syncthreads();

#pragma unroll
        for (int ks = 0; ks < 8; ks++) {
            uint32_t pa[4];
            const float* pp = &Ps[(m0 + gr) * AST + ks * 8 + gc];
            pa[0] = __float_as_uint(pp[0]);
            pa[1] = __float_as_uint(pp[8 * AST]);
            pa[2] = __float_as_uint(pp[4]);
            pa[3] = __float_as_uint(pp[8 * AST + 4]);
#pragma unroll
            for (int nt = 0; nt < 8; nt++) {
                uint32_t bv[2];
                bv[0] = __float_as_uint(Vs[(ks * 8 + gc) * AST + nt * 8 + gr]);
                bv[1] = __float_as_uint(Vs[(ks * 8 + gc + 4) * AST + nt * 8 + gr]);
                mma_tf32(o[nt], pa, bv);
            }
        }
    }

    l_lo += __shfl_xor_sync(0xffffffffu, l_lo, 1);
    l_lo += __shfl_xor_sync(0xffffffffu, l_lo, 2);
    l_hi += __shfl_xor_sync(0xffffffffu, l_hi, 1);
    l_hi += __shfl_xor_sync(0xffffffffu, l_hi, 2);
    float inv_lo = 1.f / l_lo;
    float inv_hi = 1.f / l_hi;

    float* Obase = Og + ((size_t)(b * Tt) * Hh + h) * HDim;
#pragma unroll
    for (int nt = 0; nt < 8; nt++) {
        int col = nt * 8 + 2 * gc;
        *(float2*)&Obase[(size_t)row_lo * (Hh * HDim) + col] =
            make_float2(tf(o[nt][0] * inv_lo), tf(o[nt][1] * inv_lo));
        *(float2*)&Obase[(size_t)row_hi * (Hh * HDim) + col] =
            make_float2(tf(o[nt][2] * inv_hi), tf(o[nt][3] * inv_hi));
    }
}

#define FLASH_SMEM ((128 + 64 + 64) * AST * 4)

// ============================================================
// launch
// ============================================================
extern "C" void kernel_launch(void* const* d_in, const int* in_sizes, int n_in,
                              void* d_out, int out_size)
{
    const float* x  = (const float*)d_in[0];
    const float* cs = (const float*)d_in[1];
    const float* sn = (const float*)d_in[2];
    const float* Wq = (const float*)d_in[3];
    const float* Wk = (const float*)d_in[4];
    const float* Wv = (const float*)d_in[5];
    const float* Wo = (const float*)d_in[6];
    float* out = (float*)d_out;

    float *Xtf, *QKVp, *Yp, *WqkvT, *WoT;
    cudaGetSymbolAddress((void**)&Xtf, g_Xtf);
    cudaGetSymbolAddress((void**)&QKVp, g_QKV);
    cudaGetSymbolAddress((void**)&Yp, g_Y);
    cudaGetSymbolAddress((void**)&WqkvT, g_WqkvT);
    cudaGetSymbolAddress((void**)&WoT, g_WoT);

    cudaFuncSetAttribute(gemm_mma,
                         cudaFuncAttributeMaxDynamicSharedMemorySize, GEMM_SMEM);
    cudaFuncSetAttribute(flash_attn_mma,
                         cudaFuncAttributeMaxDynamicSharedMemorySize, FLASH_SMEM);

    const int M = Bsz * Tt;  // 4096

    // operand preparation (tf32 pre-conversion folded in)
    transpose_qkv<<<dim3(48, 32), dim3(32, 8)>>>(Wq, Wk, Wv, WqkvT);
    transpose_k<<<dim3(32, 32), dim3(32, 8)>>>(Wo, WoT, Cc, Cc);
    cvt_x<<<(M * Cc / 4) / 256, 256>>>(x, Xtf);

    // fused QKV projection
    gemm_mma<<<dim3(QKVN / 128, M / 128), 256, GEMM_SMEM>>>(Xtf, WqkvT, QKVp, M, QKVN, Cc);

    // RoPE + RMSNorm on Q and K slices
    {
        int warps = M * (Hh + KVh);
        int threads = warps * 32;
        rope_rms<<<threads / 256, 256>>>(QKVp, cs, sn);
    }

    // causal GQA flash attention (tf32-rounded output)
    flash_attn_mma<<<dim3(Tt / 128, Hh, Bsz), 256, FLASH_SMEM>>>(QKVp, Yp);

    // output projection
    gemm_mma<<<dim3(Cc / 128, M / 128), 256, GEMM_SMEM>>>(Yp, WoT, out, M, Cc, Cc);
}